// round 15
// baseline (speedup 1.0000x reference)
#include <cuda_runtime.h>
#include <cuda_fp16.h>
#include <cstdint>

#define E_ 8
#define D_ 1024
#define F_ 4096
#define T_ 8192
#define TPAD (T_ + E_ * 128)     // 9216: per-expert 128-alignment padding
#define MAX_TILES 80
#define G1BLKS (32 * MAX_TILES)  // GEMM1 blocks in fused launch
#define NCHUNK 2048              // 64KB fp32 chunks per weight matrix

#define STAGES 3
#define STAGE_BYTES 32768        // A 16KB (128x64h) + B 16KB (128x64h)
#define SMEM_TOTAL (STAGES * STAGE_BYTES)   // 98304 -> 2 CTAs/SM

// ------------------- scratch (device globals; no runtime allocs) -------------------
__device__ __half g_w1h[(size_t)E_ * F_ * D_];
__device__ __half g_w2h[(size_t)E_ * D_ * F_];
__device__ __half g_hnh[(size_t)TPAD * D_];
__device__ __half g_h1h[(size_t)TPAD * F_];
__device__ float  g_alpha[T_];
__device__ int    g_assign[T_];
__device__ int    g_srt[TPAD];
__device__ int    g_counts[E_];
__device__ int    g_offsets[E_];
__device__ int    g_cursor[E_];
__device__ int    g_tileE[MAX_TILES];
__device__ int    g_tileRow[MAX_TILES];
__device__ int    g_tileEnd[MAX_TILES];
__device__ int    g_numTiles;
__device__ int    g_ready[MAX_TILES];   // GEMM1 -> GEMM2 per-Mtile counters
__device__ int    g_tick1, g_tick2;     // convert chunk tickets
__device__ int    g_cnt1[256];          // w1 panel (e*32+n) counters, target 8
__device__ int    g_cnt2[64];           // w2 panel (e*8+n)  counters, target 32

// ------------------- ptx helpers -------------------
__device__ __forceinline__ uint32_t smem_u32(const void* p) {
    return (uint32_t)__cvta_generic_to_shared(p);
}
__device__ __forceinline__ void cp16(uint32_t dst, const void* src, bool pred) {
    asm volatile("cp.async.cg.shared.global [%0], [%1], 16, %2;\n"
                 :: "r"(dst), "l"(src), "r"(pred ? 16 : 0));
}
__device__ __forceinline__ void cp_commit() { asm volatile("cp.async.commit_group;\n"); }
template <int N>
__device__ __forceinline__ void cp_wait() { asm volatile("cp.async.wait_group %0;\n" :: "n"(N)); }

__device__ __forceinline__ void ldsm_x4(uint32_t r[4], uint32_t addr) {
    asm volatile("ldmatrix.sync.aligned.m8n8.x4.shared.b16 {%0,%1,%2,%3}, [%4];"
                 : "=r"(r[0]), "=r"(r[1]), "=r"(r[2]), "=r"(r[3]) : "r"(addr));
}

__device__ __forceinline__ void mma_16x8x16(float c[4], const uint32_t a[4], const uint32_t b[2]) {
    asm volatile(
        "mma.sync.aligned.m16n8k16.row.col.f32.f16.f16.f32 "
        "{%0,%1,%2,%3}, {%4,%5,%6,%7}, {%8,%9}, {%0,%1,%2,%3};"
        : "+f"(c[0]), "+f"(c[1]), "+f"(c[2]), "+f"(c[3])
        : "r"(a[0]), "r"(a[1]), "r"(a[2]), "r"(a[3]), "r"(b[0]), "r"(b[1]));
}

// ------------------- init -------------------
__global__ void init_kernel() {
    int i = threadIdx.x;
    if (i < E_) g_counts[i] = 0;
    if (i < MAX_TILES) g_ready[i] = 0;
    if (i < 256) g_cnt1[i] = 0;
    if (i < 64) g_cnt2[i] = 0;
    if (i == 0) { g_tick1 = 0; g_tick2 = 0; }
}

// ------------------- chunk conversion helpers -------------------
// chunk = 4096 float4 (64KB fp32 -> 32KB fp16)
__device__ __forceinline__ void cvt_chunk(const float4* s4, __half2* d2, int c, int nthr) {
    const float4* s = s4 + (size_t)c * 4096;
    __half2* d = d2 + (size_t)c * 8192;
    for (int i = threadIdx.x; i < 4096; i += nthr) {
        float4 v = s[i];
        d[2 * i]     = __floats2half2_rn(v.x, v.y);
        d[2 * i + 1] = __floats2half2_rn(v.z, v.w);
    }
}

// ------------------- dedicated convert workers (co-resident, ticket-driven) ----
__global__ __launch_bounds__(128) void cvt_worker(const float* __restrict__ src, int which) {
    const float4* s4 = (const float4*)src;
    __half2* d2 = (__half2*)(which ? g_w2h : g_w1h);
    __shared__ int sh;
    while (true) {
        if (threadIdx.x == 0) sh = atomicAdd(which ? &g_tick2 : &g_tick1, 1);
        __syncthreads();
        int c = sh;
        __syncthreads();
        if (c >= NCHUNK) return;
        cvt_chunk(s4, d2, c, 128);
        __threadfence();
        __syncthreads();
        if (threadIdx.x == 0) {
            int pg = which ? ((c >> 8) * 8 + ((c & 255) >> 5))
                           : ((c >> 8) * 32 + ((c & 255) >> 3));
            atomicAdd(which ? &g_cnt2[pg] : &g_cnt1[pg], 1);
        }
        __syncthreads();
    }
}

// ------------------- routing: 2 tokens per warp -------------------
__global__ void routing_kernel(const float* __restrict__ x, const float* __restrict__ cent) {
    __shared__ float4 sc[E_][D_ / 4];
    int tid = threadIdx.x;
    for (int i = tid; i < E_ * D_ / 4; i += 256)
        ((float4*)&sc[0][0])[i] = ((const float4*)cent)[i];
    __syncthreads();

    int warp = tid >> 5, lane = tid & 31;
    int t0 = blockIdx.x * 16 + warp * 2;
    const float4* xv0 = (const float4*)(x + (size_t)t0 * D_);
    const float4* xv1 = (const float4*)(x + (size_t)(t0 + 1) * D_);

    float acc[2][E_];
#pragma unroll
    for (int e = 0; e < E_; e++) { acc[0][e] = 0.f; acc[1][e] = 0.f; }
#pragma unroll
    for (int j = 0; j < 8; j++) {
        float4 v0 = xv0[j * 32 + lane];
        float4 v1 = xv1[j * 32 + lane];
#pragma unroll
        for (int e = 0; e < E_; e++) {
            float4 c = sc[e][j * 32 + lane];
            acc[0][e] += v0.x * c.x + v0.y * c.y + v0.z * c.z + v0.w * c.w;
            acc[1][e] += v1.x * c.x + v1.y * c.y + v1.z * c.z + v1.w * c.w;
        }
    }
#pragma unroll
    for (int q = 0; q < 2; q++) {
#pragma unroll
        for (int e = 0; e < E_; e++) {
#pragma unroll
            for (int off = 16; off > 0; off >>= 1)
                acc[q][e] += __shfl_xor_sync(0xFFFFFFFFu, acc[q][e], off);
        }
        if (lane == 0) {
            int best = 0; float bv = acc[q][0];
#pragma unroll
            for (int e = 1; e < E_; e++)
                if (acc[q][e] > bv) { bv = acc[q][e]; best = e; }
            g_assign[t0 + q] = best;
            g_alpha[t0 + q] = 1.f / (1.f + expf(-bv));
            atomicAdd(&g_counts[best], 1);
        }
    }
}

// ------------------- scan -------------------
__global__ void scan_kernel() {
    if (threadIdx.x != 0) return;
    int off = 0, nt = 0;
    for (int e = 0; e < E_; e++) {
        g_offsets[e] = off;
        g_cursor[e] = off;
        int s1 = off + g_counts[e];
        for (int r = off; r < s1; r += 128) {
            g_tileE[nt]   = e;
            g_tileRow[nt] = r;
            g_tileEnd[nt] = s1;
            nt++;
        }
        off = (s1 + 127) & ~127;
    }
    g_numTiles = nt;
}

// ------------------- layernorm + scatter fused -> fp16 sorted -------------------
__global__ void ln_kernel(const float* __restrict__ x,
                          const float* __restrict__ lng,
                          const float* __restrict__ lnb) {
    int t = blockIdx.x;
    int tid = threadIdx.x;

    __shared__ int sh_s, sh_e;
    if (tid == 0) {
        int e = g_assign[t];
        int s = atomicAdd(&g_cursor[e], 1);
        g_srt[s] = t;
        sh_s = s;
        sh_e = e;
    }

    float4 v = ((const float4*)(x + (size_t)t * D_))[tid];
    float sum = v.x + v.y + v.z + v.w;
    float sq  = v.x * v.x + v.y * v.y + v.z * v.z + v.w * v.w;

    __shared__ float red[2][8];
    int warp = tid >> 5, lane = tid & 31;
#pragma unroll
    for (int off = 16; off > 0; off >>= 1) {
        sum += __shfl_xor_sync(0xFFFFFFFFu, sum, off);
        sq  += __shfl_xor_sync(0xFFFFFFFFu, sq,  off);
    }
    if (lane == 0) { red[0][warp] = sum; red[1][warp] = sq; }
    __syncthreads();
    int s = sh_s, e = sh_e;
    float tot = 0.f, totsq = 0.f;
#pragma unroll
    for (int w = 0; w < 8; w++) { tot += red[0][w]; totsq += red[1][w]; }
    float mu = tot * (1.f / D_);
    float var = totsq * (1.f / D_) - mu * mu;
    float rstd = rsqrtf(var + 1e-5f);

    float4 gg = ((const float4*)(lng + (size_t)e * D_))[tid];
    float4 bb = ((const float4*)(lnb + (size_t)e * D_))[tid];
    __half2 h0 = __floats2half2_rn((v.x - mu) * rstd * gg.x + bb.x,
                                   (v.y - mu) * rstd * gg.y + bb.y);
    __half2 h1 = __floats2half2_rn((v.z - mu) * rstd * gg.z + bb.z,
                                   (v.w - mu) * rstd * gg.w + bb.w);
    __half2* dst = (__half2*)(g_hnh + (size_t)s * D_);
    dst[2 * tid]     = h0;
    dst[2 * tid + 1] = h1;
}

// ===================================================================
// Fused grouped GEMM pair, single launch (R9/R12 GEMM config).
// GEMM1 blocks gate on w1 panel counters; GEMM2 on w2 panel + g_ready.
// While waiting, blocks STEAL convert chunks from the global ticket —
// forward progress never depends on the convert workers being scheduled.
// CTA tile M=128 x N=128, K-stage 64, 3-stage cp.async, single barrier
// per stage, 96KB smem -> 2 CTAs/SM. 8 warps as 4(m) x 2(n), warp 32x64.
// ===================================================================

template<int KDIM>
__device__ __forceinline__ void issue_stage(const __half* __restrict__ Ag,
                                            const __half* __restrict__ Bg,
                                            int k0, int rendRel,
                                            uint32_t aBase, uint32_t bBase, int tid) {
#pragma unroll
    for (int i = 0; i < 4; i++) {           // A: 1024 cp16 (128 rows x 8 chunks)
        int idx = tid + i * 256;
        int row = idx >> 3, ch = idx & 7;
        uint32_t so = (uint32_t)row * 128 + (uint32_t)((ch ^ (row & 7)) << 4);
        cp16(aBase + so, Ag + (size_t)row * KDIM + k0 + ch * 8, row < rendRel);
    }
#pragma unroll
    for (int i = 0; i < 4; i++) {           // B: 1024 cp16
        int idx = tid + i * 256;
        int row = idx >> 3, ch = idx & 7;
        uint32_t so = (uint32_t)row * 128 + (uint32_t)((ch ^ (row & 7)) << 4);
        cp16(bBase + so, Bg + (size_t)row * KDIM + k0 + ch * 8, true);
    }
}

__device__ __forceinline__ void compute_stage64(uint32_t aB, uint32_t bB,
                                                float c[2][8][4],
                                                int wm, int wn) {
    int lane = threadIdx.x & 31;
    int lr = lane & 15;
    uint32_t khoff = (uint32_t)((lane >> 4) * 16);
#pragma unroll
    for (int kk = 0; kk < 4; kk++) {
        uint32_t low = khoff + (uint32_t)(kk * 32);
        uint32_t a0[4], a1[4];
        {
            int r = wm * 32 + lr;
            ldsm_x4(a0, aB + (uint32_t)r * 128 + (low ^ (uint32_t)((r & 7) << 4)));
        }
        {
            int r = wm * 32 + 16 + lr;
            ldsm_x4(a1, aB + (uint32_t)r * 128 + (low ^ (uint32_t)((r & 7) << 4)));
        }
#pragma unroll
        for (int ni2 = 0; ni2 < 4; ni2++) {
            uint32_t q[4];
            int r = wn * 64 + ni2 * 16 + lr;
            ldsm_x4(q, bB + (uint32_t)r * 128 + (low ^ (uint32_t)((r & 7) << 4)));
            uint32_t b0[2] = {q[0], q[2]};
            uint32_t b1[2] = {q[1], q[3]};
            mma_16x8x16(c[0][2 * ni2],     a0, b0);
            mma_16x8x16(c[1][2 * ni2],     a1, b0);
            mma_16x8x16(c[0][2 * ni2 + 1], a0, b1);
            mma_16x8x16(c[1][2 * ni2 + 1], a1, b1);
        }
    }
}

// gate with stealing: wait until panel done (and ready target for GEMM2),
// converting ticket chunks while waiting.
template<bool SECOND>
__device__ __forceinline__ void gate_steal(int pg, int ti, int* shp,
                                           const float* __restrict__ wsrc) {
    const float4* s4 = (const float4*)wsrc;
    __half2* d2 = (__half2*)(SECOND ? g_w2h : g_w1h);
    int tid = threadIdx.x;
    const int target = SECOND ? 32 : 8;
    while (true) {
        if (tid == 0) {
            int* cnt = SECOND ? &g_cnt2[pg] : &g_cnt1[pg];
            bool done = atomicAdd(cnt, 0) >= target;
            if (SECOND && done) done = atomicAdd(&g_ready[ti], 0) >= 32;
            if (done) { shp[0] = -1; }
            else {
                int c = atomicAdd(SECOND ? &g_tick2 : &g_tick1, 1);
                shp[0] = (c < NCHUNK) ? c : -2;
            }
        }
        __syncthreads();
        int c = shp[0];
        __syncthreads();
        if (c == -1) break;
        if (c >= 0) {
            cvt_chunk(s4, d2, c, 256);
            __threadfence();
            __syncthreads();
            if (tid == 0) {
                int pgc = SECOND ? ((c >> 8) * 8 + ((c & 255) >> 5))
                                 : ((c >> 8) * 32 + ((c & 255) >> 3));
                atomicAdd(SECOND ? &g_cnt2[pgc] : &g_cnt1[pgc], 1);
            }
            __syncthreads();
        } else {
            __nanosleep(128);
        }
    }
}

template<int KDIM, bool SECOND>
__device__ __forceinline__ void gemm_body(int ti, int nblk, uint8_t* smem,
                                          const float* __restrict__ bias,
                                          const float* __restrict__ wsrc,
                                          const float* __restrict__ x,
                                          float* __restrict__ out) {
    if (ti >= g_numTiles) return;
    int e = g_tileE[ti], row0 = g_tileRow[ti], rend = g_tileEnd[ti];
    int n0 = nblk * 128;
    int rendRel = rend - row0;
    constexpr int NOUT = SECOND ? D_ : F_;

    // gate (+ steal conversion work while waiting)
    gate_steal<SECOND>(SECOND ? (e * 8 + nblk) : (e * 32 + nblk), ti, (int*)smem, wsrc);

    const __half* Ag = (SECOND ? g_h1h : g_hnh) + (size_t)row0 * KDIM;
    const __half* Bg = (SECOND ? g_w2h : g_w1h) + (size_t)e * ((size_t)F_ * D_) + (size_t)n0 * KDIM;
    const float*  brow = bias + (size_t)e * NOUT + n0;

    uint32_t sb = smem_u32(smem);
    int tid = threadIdx.x, warp = tid >> 5, lane = tid & 31;
    int wm = warp >> 1, wn = warp & 1;
    int g = lane >> 2, tg = lane & 3;

    float c[2][8][4];
#pragma unroll
    for (int mi = 0; mi < 2; mi++)
#pragma unroll
        for (int ni = 0; ni < 8; ni++)
#pragma unroll
            for (int k = 0; k < 4; k++) c[mi][ni][k] = 0.f;

    constexpr int CH = KDIM / 64;

    // prologue: stages 0..1
#pragma unroll
    for (int s = 0; s < 2; s++) {
        issue_stage<KDIM>(Ag, Bg, s * 64, rendRel,
                          sb + s * STAGE_BYTES, sb + s * STAGE_BYTES + 16384, tid);
        cp_commit();
    }

    int s_c = 0, s_p = 2;
#pragma unroll 1
    for (int i = 0; i < CH; i++) {
        cp_wait<1>();
        __syncthreads();   // single barrier per stage
        if (i + 2 < CH) {
            issue_stage<KDIM>(Ag, Bg, (i + 2) * 64, rendRel,
                              sb + s_p * STAGE_BYTES, sb + s_p * STAGE_BYTES + 16384, tid);
        }
        cp_commit();   // uniform commit keeps wait<1> aligned near the tail
        compute_stage64(sb + s_c * STAGE_BYTES, sb + s_c * STAGE_BYTES + 16384, c, wm, wn);
        s_c = (s_c == 2) ? 0 : s_c + 1;
        s_p = (s_p == 2) ? 0 : s_p + 1;
    }

    // ---------------- epilogue ----------------
    if (!SECOND) {
#pragma unroll
        for (int ni = 0; ni < 8; ni++) {
            int col = n0 + wn * 64 + ni * 8 + 2 * tg;
            float bi0 = __ldg(&brow[wn * 64 + ni * 8 + 2 * tg]);
            float bi1 = __ldg(&brow[wn * 64 + ni * 8 + 2 * tg + 1]);
#pragma unroll
            for (int mi = 0; mi < 2; mi++) {
                int r = row0 + wm * 32 + mi * 16 + g;
                *(__half2*)(g_h1h + (size_t)r * F_ + col) =
                    __floats2half2_rn(fmaxf(c[mi][ni][0] + bi0, 0.f),
                                      fmaxf(c[mi][ni][1] + bi1, 0.f));
                *(__half2*)(g_h1h + (size_t)(r + 8) * F_ + col) =
                    __floats2half2_rn(fmaxf(c[mi][ni][2] + bi0, 0.f),
                                      fmaxf(c[mi][ni][3] + bi1, 0.f));
            }
        }
        __threadfence();
        __syncthreads();
        if (tid == 0) atomicAdd(&g_ready[ti], 1);
    } else {
#pragma unroll
        for (int ni = 0; ni < 8; ni++) {
            int col = n0 + wn * 64 + ni * 8 + 2 * tg;
            float bi0 = __ldg(&brow[wn * 64 + ni * 8 + 2 * tg]);
            float bi1 = __ldg(&brow[wn * 64 + ni * 8 + 2 * tg + 1]);
#pragma unroll
            for (int mi = 0; mi < 2; mi++) {
                int r = row0 + wm * 32 + mi * 16 + g;
                if (r < rend) {
                    int t = g_srt[r];
                    float al = g_alpha[t];
                    float2 xv = *(const float2*)(x + (size_t)t * D_ + col);
                    float2 o;
                    o.x = xv.x + al * (c[mi][ni][0] + bi0);
                    o.y = xv.y + al * (c[mi][ni][1] + bi1);
                    *(float2*)(out + (size_t)t * D_ + col) = o;
                }
                if (r + 8 < rend) {
                    int t = g_srt[r + 8];
                    float al = g_alpha[t];
                    float2 xv = *(const float2*)(x + (size_t)t * D_ + col);
                    float2 o;
                    o.x = xv.x + al * (c[mi][ni][2] + bi0);
                    o.y = xv.y + al * (c[mi][ni][3] + bi1);
                    *(float2*)(out + (size_t)t * D_ + col) = o;
                }
            }
        }
    }
}

__global__ __launch_bounds__(256, 2) void fused_gemm(const float* __restrict__ b1,
                                                     const float* __restrict__ b2,
                                                     const float* __restrict__ w1src,
                                                     const float* __restrict__ w2src,
                                                     const float* __restrict__ x,
                                                     float* __restrict__ out) {
    extern __shared__ __align__(1024) uint8_t smem[];
    int bid = blockIdx.x;
    if (bid < G1BLKS) {
        gemm_body<D_, false>(bid >> 5, bid & 31, smem, b1, w1src, x, out);
    } else {
        int r = bid - G1BLKS;
        gemm_body<F_, true>(r >> 3, r & 7, smem, b2, w2src, x, out);
    }
}

// ------------------- launch -------------------
extern "C" void kernel_launch(void* const* d_in, const int* in_sizes, int n_in,
                              void* d_out, int out_size) {
    const float* x    = (const float*)d_in[0];
    const float* cent = (const float*)d_in[1];
    const float* lng  = (const float*)d_in[2];
    const float* lnb  = (const float*)d_in[3];
    const float* w1   = (const float*)d_in[4];
    const float* b1   = (const float*)d_in[5];
    const float* w2   = (const float*)d_in[6];
    const float* b2   = (const float*)d_in[7];
    float* out = (float*)d_out;

    static cudaStream_t sA = nullptr, sB = nullptr;
    static cudaEvent_t eFork = nullptr, eC1 = nullptr, eC2 = nullptr;
    if (!sA) {
        cudaStreamCreateWithFlags(&sA, cudaStreamNonBlocking);
        cudaStreamCreateWithFlags(&sB, cudaStreamNonBlocking);
        cudaEventCreateWithFlags(&eFork, cudaEventDisableTiming);
        cudaEventCreateWithFlags(&eC1, cudaEventDisableTiming);
        cudaEventCreateWithFlags(&eC2, cudaEventDisableTiming);
        cudaFuncSetAttribute(fused_gemm, cudaFuncAttributeMaxDynamicSharedMemorySize, SMEM_TOTAL);
    }

    // init counters first; converts (ticket-driven) fork after init
    init_kernel<<<1, 256>>>();
    cudaEventRecord(eFork, 0);
    cudaStreamWaitEvent(sA, eFork, 0);
    cudaStreamWaitEvent(sB, eFork, 0);
    cvt_worker<<<1024, 128, 0, sA>>>(w1, 0);
    cudaEventRecord(eC1, sA);
    cvt_worker<<<1024, 128, 0, sB>>>(w2, 1);
    cudaEventRecord(eC2, sB);

    // routing chain on main stream (overlaps converts)
    routing_kernel<<<T_ / 16, 256>>>(x, cent);
    scan_kernel<<<1, 1>>>();
    ln_kernel<<<T_, 256>>>(x, lng, lnb);

    // fused GEMMs launch immediately; blocks gate+steal on weight panels
    fused_gemm<<<G1BLKS + 8 * MAX_TILES, 256, SMEM_TOTAL>>>(b1, b2, w1, w2, x, out);

    // join side streams (non-serializing: after the fused launch)
    cudaStreamWaitEvent(0, eC1, 0);
    cudaStreamWaitEvent(0, eC2, 0);
}

// round 16
// speedup vs baseline: 1.0161x; 1.0161x over previous
#include <cuda_runtime.h>
#include <cuda_fp16.h>
#include <cstdint>

#define E_ 8
#define D_ 1024
#define F_ 4096
#define T_ 8192
#define TPAD (T_ + E_ * 128)     // 9216: per-expert 128-alignment padding
#define MAX_TILES 80
#define G1BLKS (32 * MAX_TILES)  // GEMM1 blocks in fused launch
#define NCHUNK 2048              // w2: 64KB fp32 chunks

#define STAGES 3
#define STAGE_BYTES 32768        // A 16KB (128x64h) + B 16KB (128x64h)
#define SMEM_TOTAL (STAGES * STAGE_BYTES)   // 98304 -> 2 CTAs/SM

// ------------------- scratch (device globals; no runtime allocs) -------------------
__device__ __half g_w1h[(size_t)E_ * F_ * D_];
__device__ __half g_w2h[(size_t)E_ * D_ * F_];
__device__ __half g_hnh[(size_t)TPAD * D_];
__device__ __half g_h1h[(size_t)TPAD * F_];
__device__ float  g_alpha[T_];
__device__ int    g_assign[T_];
__device__ int    g_srt[TPAD];
__device__ int    g_counts[E_];
__device__ int    g_offsets[E_];
__device__ int    g_cursor[E_];
__device__ int    g_tileE[MAX_TILES];
__device__ int    g_tileRow[MAX_TILES];
__device__ int    g_tileEnd[MAX_TILES];
__device__ int    g_numTiles;
__device__ int    g_ready[MAX_TILES];   // GEMM1 -> GEMM2 per-Mtile counters
__device__ int    g_tick2;              // w2 convert chunk ticket
__device__ int    g_w2cnt;              // w2 chunks completed (target NCHUNK)

// ------------------- ptx helpers -------------------
__device__ __forceinline__ uint32_t smem_u32(const void* p) {
    return (uint32_t)__cvta_generic_to_shared(p);
}
__device__ __forceinline__ void cp16(uint32_t dst, const void* src, bool pred) {
    asm volatile("cp.async.cg.shared.global [%0], [%1], 16, %2;\n"
                 :: "r"(dst), "l"(src), "r"(pred ? 16 : 0));
}
__device__ __forceinline__ void cp_commit() { asm volatile("cp.async.commit_group;\n"); }
template <int N>
__device__ __forceinline__ void cp_wait() { asm volatile("cp.async.wait_group %0;\n" :: "n"(N)); }

__device__ __forceinline__ void ldsm_x4(uint32_t r[4], uint32_t addr) {
    asm volatile("ldmatrix.sync.aligned.m8n8.x4.shared.b16 {%0,%1,%2,%3}, [%4];"
                 : "=r"(r[0]), "=r"(r[1]), "=r"(r[2]), "=r"(r[3]) : "r"(addr));
}

__device__ __forceinline__ void mma_16x8x16(float c[4], const uint32_t a[4], const uint32_t b[2]) {
    asm volatile(
        "mma.sync.aligned.m16n8k16.row.col.f32.f16.f16.f32 "
        "{%0,%1,%2,%3}, {%4,%5,%6,%7}, {%8,%9}, {%0,%1,%2,%3};"
        : "+f"(c[0]), "+f"(c[1]), "+f"(c[2]), "+f"(c[3])
        : "r"(a[0]), "r"(a[1]), "r"(a[2]), "r"(a[3]), "r"(b[0]), "r"(b[1]));
}

// ------------------- init -------------------
__global__ void init_kernel() {
    int i = threadIdx.x;
    if (i < E_) g_counts[i] = 0;
    if (i < MAX_TILES) g_ready[i] = 0;
    if (i == 0) { g_tick2 = 0; g_w2cnt = 0; }
}

// ------------------- w1 fp32 -> fp16 (runs alone first, full BW) -------------------
__global__ void convert_w1(const float* __restrict__ src) {
    size_t n4 = ((size_t)E_ * F_ * D_) / 4;
    size_t stride = (size_t)gridDim.x * blockDim.x;
    for (size_t i = (size_t)blockIdx.x * blockDim.x + threadIdx.x; i < n4; i += stride) {
        float4 v = ((const float4*)src)[i];
        ((__half2*)g_w1h)[2 * i]     = __floats2half2_rn(v.x, v.y);
        ((__half2*)g_w1h)[2 * i + 1] = __floats2half2_rn(v.z, v.w);
    }
}

// ------------------- w2 chunk conversion (ticket-driven) -------------------
// chunk = 4096 float4 (64KB fp32 -> 32KB fp16)
__device__ __forceinline__ void cvt_chunk_w2(const float4* s4, int c, int nthr) {
    const float4* s = s4 + (size_t)c * 4096;
    __half2* d = (__half2*)g_w2h + (size_t)c * 8192;
    for (int i = threadIdx.x; i < 4096; i += nthr) {
        float4 v = s[i];
        d[2 * i]     = __floats2half2_rn(v.x, v.y);
        d[2 * i + 1] = __floats2half2_rn(v.z, v.w);
    }
}

__global__ __launch_bounds__(256) void cvt_worker_w2(const float* __restrict__ src) {
    const float4* s4 = (const float4*)src;
    __shared__ int sh;
    while (true) {
        if (threadIdx.x == 0) sh = atomicAdd(&g_tick2, 1);
        __syncthreads();
        int c = sh;
        __syncthreads();
        if (c >= NCHUNK) return;
        cvt_chunk_w2(s4, c, 256);
        __threadfence();
        __syncthreads();
        if (threadIdx.x == 0) atomicAdd(&g_w2cnt, 1);
        __syncthreads();
    }
}

// ------------------- routing: 2 tokens per warp -------------------
__global__ void routing_kernel(const float* __restrict__ x, const float* __restrict__ cent) {
    __shared__ float4 sc[E_][D_ / 4];
    int tid = threadIdx.x;
    for (int i = tid; i < E_ * D_ / 4; i += 256)
        ((float4*)&sc[0][0])[i] = ((const float4*)cent)[i];
    __syncthreads();

    int warp = tid >> 5, lane = tid & 31;
    int t0 = blockIdx.x * 16 + warp * 2;
    const float4* xv0 = (const float4*)(x + (size_t)t0 * D_);
    const float4* xv1 = (const float4*)(x + (size_t)(t0 + 1) * D_);

    float acc[2][E_];
#pragma unroll
    for (int e = 0; e < E_; e++) { acc[0][e] = 0.f; acc[1][e] = 0.f; }
#pragma unroll
    for (int j = 0; j < 8; j++) {
        float4 v0 = xv0[j * 32 + lane];
        float4 v1 = xv1[j * 32 + lane];
#pragma unroll
        for (int e = 0; e < E_; e++) {
            float4 c = sc[e][j * 32 + lane];
            acc[0][e] += v0.x * c.x + v0.y * c.y + v0.z * c.z + v0.w * c.w;
            acc[1][e] += v1.x * c.x + v1.y * c.y + v1.z * c.z + v1.w * c.w;
        }
    }
#pragma unroll
    for (int q = 0; q < 2; q++) {
#pragma unroll
        for (int e = 0; e < E_; e++) {
#pragma unroll
            for (int off = 16; off > 0; off >>= 1)
                acc[q][e] += __shfl_xor_sync(0xFFFFFFFFu, acc[q][e], off);
        }
        if (lane == 0) {
            int best = 0; float bv = acc[q][0];
#pragma unroll
            for (int e = 1; e < E_; e++)
                if (acc[q][e] > bv) { bv = acc[q][e]; best = e; }
            g_assign[t0 + q] = best;
            g_alpha[t0 + q] = 1.f / (1.f + expf(-bv));
            atomicAdd(&g_counts[best], 1);
        }
    }
}

// ------------------- scan -------------------
__global__ void scan_kernel() {
    if (threadIdx.x != 0) return;
    int off = 0, nt = 0;
    for (int e = 0; e < E_; e++) {
        g_offsets[e] = off;
        g_cursor[e] = off;
        int s1 = off + g_counts[e];
        for (int r = off; r < s1; r += 128) {
            g_tileE[nt]   = e;
            g_tileRow[nt] = r;
            g_tileEnd[nt] = s1;
            nt++;
        }
        off = (s1 + 127) & ~127;
    }
    g_numTiles = nt;
}

// ------------------- layernorm + scatter fused -> fp16 sorted -------------------
__global__ void ln_kernel(const float* __restrict__ x,
                          const float* __restrict__ lng,
                          const float* __restrict__ lnb) {
    int t = blockIdx.x;
    int tid = threadIdx.x;

    __shared__ int sh_s, sh_e;
    if (tid == 0) {
        int e = g_assign[t];
        int s = atomicAdd(&g_cursor[e], 1);
        g_srt[s] = t;
        sh_s = s;
        sh_e = e;
    }

    float4 v = ((const float4*)(x + (size_t)t * D_))[tid];
    float sum = v.x + v.y + v.z + v.w;
    float sq  = v.x * v.x + v.y * v.y + v.z * v.z + v.w * v.w;

    __shared__ float red[2][8];
    int warp = tid >> 5, lane = tid & 31;
#pragma unroll
    for (int off = 16; off > 0; off >>= 1) {
        sum += __shfl_xor_sync(0xFFFFFFFFu, sum, off);
        sq  += __shfl_xor_sync(0xFFFFFFFFu, sq,  off);
    }
    if (lane == 0) { red[0][warp] = sum; red[1][warp] = sq; }
    __syncthreads();
    int s = sh_s, e = sh_e;
    float tot = 0.f, totsq = 0.f;
#pragma unroll
    for (int w = 0; w < 8; w++) { tot += red[0][w]; totsq += red[1][w]; }
    float mu = tot * (1.f / D_);
    float var = totsq * (1.f / D_) - mu * mu;
    float rstd = rsqrtf(var + 1e-5f);

    float4 gg = ((const float4*)(lng + (size_t)e * D_))[tid];
    float4 bb = ((const float4*)(lnb + (size_t)e * D_))[tid];
    __half2 h0 = __floats2half2_rn((v.x - mu) * rstd * gg.x + bb.x,
                                   (v.y - mu) * rstd * gg.y + bb.y);
    __half2 h1 = __floats2half2_rn((v.z - mu) * rstd * gg.z + bb.z,
                                   (v.w - mu) * rstd * gg.w + bb.w);
    __half2* dst = (__half2*)(g_hnh + (size_t)s * D_);
    dst[2 * tid]     = h0;
    dst[2 * tid + 1] = h1;
}

// ===================================================================
// Fused grouped GEMM pair, single launch (R9/R12 GEMM config).
// GEMM1 blocks: NO gating (w1 converted before launch via event).
// GEMM2 blocks: gate on g_w2cnt == NCHUNK (stealing w2 chunks from the
// ticket while waiting -> no dependence on worker co-scheduling), then
// the usual g_ready[ti] == 32 producer wait.
// CTA tile M=128 x N=128, K-stage 64, 3-stage cp.async, single barrier
// per stage, 96KB smem -> 2 CTAs/SM. 8 warps as 4(m) x 2(n), warp 32x64.
// ===================================================================

template<int KDIM>
__device__ __forceinline__ void issue_stage(const __half* __restrict__ Ag,
                                            const __half* __restrict__ Bg,
                                            int k0, int rendRel,
                                            uint32_t aBase, uint32_t bBase, int tid) {
#pragma unroll
    for (int i = 0; i < 4; i++) {           // A: 1024 cp16 (128 rows x 8 chunks)
        int idx = tid + i * 256;
        int row = idx >> 3, ch = idx & 7;
        uint32_t so = (uint32_t)row * 128 + (uint32_t)((ch ^ (row & 7)) << 4);
        cp16(aBase + so, Ag + (size_t)row * KDIM + k0 + ch * 8, row < rendRel);
    }
#pragma unroll
    for (int i = 0; i < 4; i++) {           // B: 1024 cp16
        int idx = tid + i * 256;
        int row = idx >> 3, ch = idx & 7;
        uint32_t so = (uint32_t)row * 128 + (uint32_t)((ch ^ (row & 7)) << 4);
        cp16(bBase + so, Bg + (size_t)row * KDIM + k0 + ch * 8, true);
    }
}

__device__ __forceinline__ void compute_stage64(uint32_t aB, uint32_t bB,
                                                float c[2][8][4],
                                                int wm, int wn) {
    int lane = threadIdx.x & 31;
    int lr = lane & 15;
    uint32_t khoff = (uint32_t)((lane >> 4) * 16);
#pragma unroll
    for (int kk = 0; kk < 4; kk++) {
        uint32_t low = khoff + (uint32_t)(kk * 32);
        uint32_t a0[4], a1[4];
        {
            int r = wm * 32 + lr;
            ldsm_x4(a0, aB + (uint32_t)r * 128 + (low ^ (uint32_t)((r & 7) << 4)));
        }
        {
            int r = wm * 32 + 16 + lr;
            ldsm_x4(a1, aB + (uint32_t)r * 128 + (low ^ (uint32_t)((r & 7) << 4)));
        }
#pragma unroll
        for (int ni2 = 0; ni2 < 4; ni2++) {
            uint32_t q[4];
            int r = wn * 64 + ni2 * 16 + lr;
            ldsm_x4(q, bB + (uint32_t)r * 128 + (low ^ (uint32_t)((r & 7) << 4)));
            uint32_t b0[2] = {q[0], q[2]};
            uint32_t b1[2] = {q[1], q[3]};
            mma_16x8x16(c[0][2 * ni2],     a0, b0);
            mma_16x8x16(c[1][2 * ni2],     a1, b0);
            mma_16x8x16(c[0][2 * ni2 + 1], a0, b1);
            mma_16x8x16(c[1][2 * ni2 + 1], a1, b1);
        }
    }
}

// GEMM2 gate: ensure w2 fully converted (stealing chunks while waiting)
__device__ __forceinline__ void gate_w2(int* shp, const float* __restrict__ w2src) {
    const float4* s4 = (const float4*)w2src;
    int tid = threadIdx.x;
    while (true) {
        if (tid == 0) {
            if (atomicAdd(&g_w2cnt, 0) >= NCHUNK) shp[0] = -1;
            else {
                int c = atomicAdd(&g_tick2, 1);
                shp[0] = (c < NCHUNK) ? c : -2;
            }
        }
        __syncthreads();
        int c = shp[0];
        __syncthreads();
        if (c == -1) break;
        if (c >= 0) {
            cvt_chunk_w2(s4, c, 256);
            __threadfence();
            __syncthreads();
            if (tid == 0) atomicAdd(&g_w2cnt, 1);
            __syncthreads();
        } else {
            __nanosleep(128);
        }
    }
}

template<int KDIM, bool SECOND>
__device__ __forceinline__ void gemm_body(int ti, int nblk, uint8_t* smem,
                                          const float* __restrict__ bias,
                                          const float* __restrict__ w2src,
                                          const float* __restrict__ x,
                                          float* __restrict__ out) {
    if (ti >= g_numTiles) return;
    int e = g_tileE[ti], row0 = g_tileRow[ti], rend = g_tileEnd[ti];
    int n0 = nblk * 128;
    int rendRel = rend - row0;
    constexpr int NOUT = SECOND ? D_ : F_;

    if (SECOND) {
        gate_w2((int*)smem, w2src);
        if (threadIdx.x == 0) {
            while (atomicAdd(&g_ready[ti], 0) < 32) __nanosleep(64);
        }
        __syncthreads();
    }

    const __half* Ag = (SECOND ? g_h1h : g_hnh) + (size_t)row0 * KDIM;
    const __half* Bg = (SECOND ? g_w2h : g_w1h) + (size_t)e * ((size_t)F_ * D_) + (size_t)n0 * KDIM;
    const float*  brow = bias + (size_t)e * NOUT + n0;

    uint32_t sb = smem_u32(smem);
    int tid = threadIdx.x, warp = tid >> 5, lane = tid & 31;
    int wm = warp >> 1, wn = warp & 1;
    int g = lane >> 2, tg = lane & 3;

    float c[2][8][4];
#pragma unroll
    for (int mi = 0; mi < 2; mi++)
#pragma unroll
        for (int ni = 0; ni < 8; ni++)
#pragma unroll
            for (int k = 0; k < 4; k++) c[mi][ni][k] = 0.f;

    constexpr int CH = KDIM / 64;

    // prologue: stages 0..1
#pragma unroll
    for (int s = 0; s < 2; s++) {
        issue_stage<KDIM>(Ag, Bg, s * 64, rendRel,
                          sb + s * STAGE_BYTES, sb + s * STAGE_BYTES + 16384, tid);
        cp_commit();
    }

    int s_c = 0, s_p = 2;
#pragma unroll 1
    for (int i = 0; i < CH; i++) {
        cp_wait<1>();
        __syncthreads();   // single barrier per stage
        if (i + 2 < CH) {
            issue_stage<KDIM>(Ag, Bg, (i + 2) * 64, rendRel,
                              sb + s_p * STAGE_BYTES, sb + s_p * STAGE_BYTES + 16384, tid);
        }
        cp_commit();   // uniform commit keeps wait<1> aligned near the tail
        compute_stage64(sb + s_c * STAGE_BYTES, sb + s_c * STAGE_BYTES + 16384, c, wm, wn);
        s_c = (s_c == 2) ? 0 : s_c + 1;
        s_p = (s_p == 2) ? 0 : s_p + 1;
    }

    // ---------------- epilogue ----------------
    if (!SECOND) {
#pragma unroll
        for (int ni = 0; ni < 8; ni++) {
            int col = n0 + wn * 64 + ni * 8 + 2 * tg;
            float bi0 = __ldg(&brow[wn * 64 + ni * 8 + 2 * tg]);
            float bi1 = __ldg(&brow[wn * 64 + ni * 8 + 2 * tg + 1]);
#pragma unroll
            for (int mi = 0; mi < 2; mi++) {
                int r = row0 + wm * 32 + mi * 16 + g;
                *(__half2*)(g_h1h + (size_t)r * F_ + col) =
                    __floats2half2_rn(fmaxf(c[mi][ni][0] + bi0, 0.f),
                                      fmaxf(c[mi][ni][1] + bi1, 0.f));
                *(__half2*)(g_h1h + (size_t)(r + 8) * F_ + col) =
                    __floats2half2_rn(fmaxf(c[mi][ni][2] + bi0, 0.f),
                                      fmaxf(c[mi][ni][3] + bi1, 0.f));
            }
        }
        __threadfence();
        __syncthreads();
        if (tid == 0) atomicAdd(&g_ready[ti], 1);
    } else {
#pragma unroll
        for (int ni = 0; ni < 8; ni++) {
            int col = n0 + wn * 64 + ni * 8 + 2 * tg;
            float bi0 = __ldg(&brow[wn * 64 + ni * 8 + 2 * tg]);
            float bi1 = __ldg(&brow[wn * 64 + ni * 8 + 2 * tg + 1]);
#pragma unroll
            for (int mi = 0; mi < 2; mi++) {
                int r = row0 + wm * 32 + mi * 16 + g;
                if (r < rend) {
                    int t = g_srt[r];
                    float al = g_alpha[t];
                    float2 xv = *(const float2*)(x + (size_t)t * D_ + col);
                    float2 o;
                    o.x = xv.x + al * (c[mi][ni][0] + bi0);
                    o.y = xv.y + al * (c[mi][ni][1] + bi1);
                    *(float2*)(out + (size_t)t * D_ + col) = o;
                }
                if (r + 8 < rend) {
                    int t = g_srt[r + 8];
                    float al = g_alpha[t];
                    float2 xv = *(const float2*)(x + (size_t)t * D_ + col);
                    float2 o;
                    o.x = xv.x + al * (c[mi][ni][2] + bi0);
                    o.y = xv.y + al * (c[mi][ni][3] + bi1);
                    *(float2*)(out + (size_t)t * D_ + col) = o;
                }
            }
        }
    }
}

__global__ __launch_bounds__(256, 2) void fused_gemm(const float* __restrict__ b1,
                                                     const float* __restrict__ b2,
                                                     const float* __restrict__ w2src,
                                                     const float* __restrict__ x,
                                                     float* __restrict__ out) {
    extern __shared__ __align__(1024) uint8_t smem[];
    int bid = blockIdx.x;
    if (bid < G1BLKS) {
        gemm_body<D_, false>(bid >> 5, bid & 31, smem, b1, w2src, x, out);
    } else {
        int r = bid - G1BLKS;
        gemm_body<F_, true>(r >> 3, r & 7, smem, b2, w2src, x, out);
    }
}

// ------------------- launch -------------------
extern "C" void kernel_launch(void* const* d_in, const int* in_sizes, int n_in,
                              void* d_out, int out_size) {
    const float* x    = (const float*)d_in[0];
    const float* cent = (const float*)d_in[1];
    const float* lng  = (const float*)d_in[2];
    const float* lnb  = (const float*)d_in[3];
    const float* w1   = (const float*)d_in[4];
    const float* b1   = (const float*)d_in[5];
    const float* w2   = (const float*)d_in[6];
    const float* b2   = (const float*)d_in[7];
    float* out = (float*)d_out;

    static cudaStream_t sA = nullptr;
    static cudaEvent_t eFork = nullptr, eW1 = nullptr, eC2 = nullptr;
    if (!sA) {
        cudaStreamCreateWithFlags(&sA, cudaStreamNonBlocking);
        cudaEventCreateWithFlags(&eFork, cudaEventDisableTiming);
        cudaEventCreateWithFlags(&eW1, cudaEventDisableTiming);
        cudaEventCreateWithFlags(&eC2, cudaEventDisableTiming);
        cudaFuncSetAttribute(fused_gemm, cudaFuncAttributeMaxDynamicSharedMemorySize, SMEM_TOTAL);
    }

    // init first (ticket/counters), then fork the weight pipeline onto sA:
    // w1 converts ALONE at full HBM bandwidth, then w2 workers start and
    // run co-resident with GEMM1 of the fused kernel.
    init_kernel<<<1, 128>>>();
    cudaEventRecord(eFork, 0);
    cudaStreamWaitEvent(sA, eFork, 0);
    convert_w1<<<4096, 256, 0, sA>>>(w1);
    cudaEventRecord(eW1, sA);
    cvt_worker_w2<<<2048, 256, 0, sA>>>(w2);
    cudaEventRecord(eC2, sA);

    // routing chain on main stream (overlaps w1 convert)
    routing_kernel<<<T_ / 16, 256>>>(x, cent);
    scan_kernel<<<1, 1>>>();
    ln_kernel<<<T_, 256>>>(x, lng, lnb);

    // fused GEMMs: gate only on w1 (event); w2 is gated in-kernel by GEMM2
    cudaStreamWaitEvent(0, eW1, 0);
    fused_gemm<<<G1BLKS + 8 * MAX_TILES, 256, SMEM_TOTAL>>>(b1, b2, w2, x, out);

    // join the worker stream (after the fused launch; non-serializing)
    cudaStreamWaitEvent(0, eC2, 0);
}

// round 17
// speedup vs baseline: 1.0259x; 1.0096x over previous
#include <cuda_runtime.h>
#include <cuda_fp16.h>
#include <cstdint>

#define E_ 8
#define D_ 1024
#define F_ 4096
#define T_ 8192
#define TPAD (T_ + E_ * 128)     // 9216: per-expert 128-alignment padding
#define MAX_TILES 80
#define G1BLKS (32 * MAX_TILES)  // GEMM1 blocks in fused launch
#define NCHUNK 2048              // w2: 64KB fp32 chunks

#define STAGES 3
#define STAGE_BYTES 32768        // A 16KB (128x64h) + B 16KB (128x64h)
#define SMEM_TOTAL (STAGES * STAGE_BYTES)   // 98304 -> 2 CTAs/SM

// ------------------- scratch (device globals; no runtime allocs) -------------------
__device__ __half g_w1h[(size_t)E_ * F_ * D_];
__device__ __half g_w2h[(size_t)E_ * D_ * F_];
__device__ __half g_hnh[(size_t)TPAD * D_];
__device__ __half g_h1h[(size_t)TPAD * F_];
__device__ float  g_alpha[T_];
__device__ int    g_assign[T_];
__device__ int    g_srt[TPAD];
__device__ int    g_counts[E_];
__device__ int    g_offsets[E_];
__device__ int    g_cursor[E_];
__device__ int    g_tileE[MAX_TILES];
__device__ int    g_tileRow[MAX_TILES];
__device__ int    g_tileEnd[MAX_TILES];
__device__ int    g_numTiles;
__device__ int    g_ready[MAX_TILES];   // GEMM1 -> GEMM2 per-Mtile counters
__device__ int    g_tick2;              // w2 convert chunk ticket
__device__ int    g_w2cnt;              // w2 chunks completed (target NCHUNK)

// ------------------- ptx helpers -------------------
__device__ __forceinline__ uint32_t smem_u32(const void* p) {
    return (uint32_t)__cvta_generic_to_shared(p);
}
__device__ __forceinline__ void cp16(uint32_t dst, const void* src, bool pred) {
    asm volatile("cp.async.cg.shared.global [%0], [%1], 16, %2;\n"
                 :: "r"(dst), "l"(src), "r"(pred ? 16 : 0));
}
__device__ __forceinline__ void cp_commit() { asm volatile("cp.async.commit_group;\n"); }
template <int N>
__device__ __forceinline__ void cp_wait() { asm volatile("cp.async.wait_group %0;\n" :: "n"(N)); }

__device__ __forceinline__ void ldsm_x4(uint32_t r[4], uint32_t addr) {
    asm volatile("ldmatrix.sync.aligned.m8n8.x4.shared.b16 {%0,%1,%2,%3}, [%4];"
                 : "=r"(r[0]), "=r"(r[1]), "=r"(r[2]), "=r"(r[3]) : "r"(addr));
}

__device__ __forceinline__ void mma_16x8x16(float c[4], const uint32_t a[4], const uint32_t b[2]) {
    asm volatile(
        "mma.sync.aligned.m16n8k16.row.col.f32.f16.f16.f32 "
        "{%0,%1,%2,%3}, {%4,%5,%6,%7}, {%8,%9}, {%0,%1,%2,%3};"
        : "+f"(c[0]), "+f"(c[1]), "+f"(c[2]), "+f"(c[3])
        : "r"(a[0]), "r"(a[1]), "r"(a[2]), "r"(a[3]), "r"(b[0]), "r"(b[1]));
}

// ------------------- init -------------------
__global__ void init_kernel() {
    int i = threadIdx.x;
    if (i < E_) g_counts[i] = 0;
    if (i < MAX_TILES) g_ready[i] = 0;
    if (i == 0) { g_tick2 = 0; g_w2cnt = 0; }
}

// ------------------- w1 fp32 -> fp16 (runs alone first, full BW) -------------------
__global__ void convert_w1(const float* __restrict__ src) {
    size_t n4 = ((size_t)E_ * F_ * D_) / 4;
    size_t stride = (size_t)gridDim.x * blockDim.x;
    for (size_t i = (size_t)blockIdx.x * blockDim.x + threadIdx.x; i < n4; i += stride) {
        float4 v = __ldcs((const float4*)src + i);
        ((__half2*)g_w1h)[2 * i]     = __floats2half2_rn(v.x, v.y);
        ((__half2*)g_w1h)[2 * i + 1] = __floats2half2_rn(v.z, v.w);
    }
}

// ------------------- w2 chunk conversion (ticket-driven) -------------------
// chunk = 4096 float4 (64KB fp32 -> 32KB fp16). Streaming hints: keep both
// the fp32 source and fp16 result OUT of L2 (consumed much later) so the
// co-resident GEMM1's B panels stay L2-hot.
__device__ __forceinline__ void cvt_chunk_w2(const float4* s4, int c, int nthr) {
    const float4* s = s4 + (size_t)c * 4096;
    float4* d = (float4*)((__half2*)g_w2h + (size_t)c * 8192);
    for (int i = threadIdx.x; i < 4096; i += nthr) {
        float4 v = __ldcs(s + i);
        __half2 h0 = __floats2half2_rn(v.x, v.y);
        __half2 h1 = __floats2half2_rn(v.z, v.w);
        if ((i & 1) == 0) {
            // pair adjacent half2s into a 16B streaming store every 2 iters is
            // complex; do 8B streaming stores instead
        }
        __stcs((__half2*)d + 2 * i, h0);
        __stcs((__half2*)d + 2 * i + 1, h1);
    }
}

// one persistent worker block per SM: trickle conversion, minimal GEMM interference
__global__ __launch_bounds__(256) void cvt_worker_w2(const float* __restrict__ src) {
    const float4* s4 = (const float4*)src;
    __shared__ int sh;
    while (true) {
        if (threadIdx.x == 0) sh = atomicAdd(&g_tick2, 1);
        __syncthreads();
        int c = sh;
        __syncthreads();
        if (c >= NCHUNK) return;
        cvt_chunk_w2(s4, c, 256);
        __threadfence();
        __syncthreads();
        if (threadIdx.x == 0) atomicAdd(&g_w2cnt, 1);
        __syncthreads();
    }
}

// ------------------- routing: 2 tokens per warp -------------------
__global__ void routing_kernel(const float* __restrict__ x, const float* __restrict__ cent) {
    __shared__ float4 sc[E_][D_ / 4];
    int tid = threadIdx.x;
    for (int i = tid; i < E_ * D_ / 4; i += 256)
        ((float4*)&sc[0][0])[i] = ((const float4*)cent)[i];
    __syncthreads();

    int warp = tid >> 5, lane = tid & 31;
    int t0 = blockIdx.x * 16 + warp * 2;
    const float4* xv0 = (const float4*)(x + (size_t)t0 * D_);
    const float4* xv1 = (const float4*)(x + (size_t)(t0 + 1) * D_);

    float acc[2][E_];
#pragma unroll
    for (int e = 0; e < E_; e++) { acc[0][e] = 0.f; acc[1][e] = 0.f; }
#pragma unroll
    for (int j = 0; j < 8; j++) {
        float4 v0 = xv0[j * 32 + lane];
        float4 v1 = xv1[j * 32 + lane];
#pragma unroll
        for (int e = 0; e < E_; e++) {
            float4 c = sc[e][j * 32 + lane];
            acc[0][e] += v0.x * c.x + v0.y * c.y + v0.z * c.z + v0.w * c.w;
            acc[1][e] += v1.x * c.x + v1.y * c.y + v1.z * c.z + v1.w * c.w;
        }
    }
#pragma unroll
    for (int q = 0; q < 2; q++) {
#pragma unroll
        for (int e = 0; e < E_; e++) {
#pragma unroll
            for (int off = 16; off > 0; off >>= 1)
                acc[q][e] += __shfl_xor_sync(0xFFFFFFFFu, acc[q][e], off);
        }
        if (lane == 0) {
            int best = 0; float bv = acc[q][0];
#pragma unroll
            for (int e = 1; e < E_; e++)
                if (acc[q][e] > bv) { bv = acc[q][e]; best = e; }
            g_assign[t0 + q] = best;
            g_alpha[t0 + q] = 1.f / (1.f + expf(-bv));
            atomicAdd(&g_counts[best], 1);
        }
    }
}

// ------------------- scan -------------------
__global__ void scan_kernel() {
    if (threadIdx.x != 0) return;
    int off = 0, nt = 0;
    for (int e = 0; e < E_; e++) {
        g_offsets[e] = off;
        g_cursor[e] = off;
        int s1 = off + g_counts[e];
        for (int r = off; r < s1; r += 128) {
            g_tileE[nt]   = e;
            g_tileRow[nt] = r;
            g_tileEnd[nt] = s1;
            nt++;
        }
        off = (s1 + 127) & ~127;
    }
    g_numTiles = nt;
}

// ------------------- layernorm + scatter fused -> fp16 sorted -------------------
__global__ void ln_kernel(const float* __restrict__ x,
                          const float* __restrict__ lng,
                          const float* __restrict__ lnb) {
    int t = blockIdx.x;
    int tid = threadIdx.x;

    __shared__ int sh_s, sh_e;
    if (tid == 0) {
        int e = g_assign[t];
        int s = atomicAdd(&g_cursor[e], 1);
        g_srt[s] = t;
        sh_s = s;
        sh_e = e;
    }

    float4 v = ((const float4*)(x + (size_t)t * D_))[tid];
    float sum = v.x + v.y + v.z + v.w;
    float sq  = v.x * v.x + v.y * v.y + v.z * v.z + v.w * v.w;

    __shared__ float red[2][8];
    int warp = tid >> 5, lane = tid & 31;
#pragma unroll
    for (int off = 16; off > 0; off >>= 1) {
        sum += __shfl_xor_sync(0xFFFFFFFFu, sum, off);
        sq  += __shfl_xor_sync(0xFFFFFFFFu, sq,  off);
    }
    if (lane == 0) { red[0][warp] = sum; red[1][warp] = sq; }
    __syncthreads();
    int s = sh_s, e = sh_e;
    float tot = 0.f, totsq = 0.f;
#pragma unroll
    for (int w = 0; w < 8; w++) { tot += red[0][w]; totsq += red[1][w]; }
    float mu = tot * (1.f / D_);
    float var = totsq * (1.f / D_) - mu * mu;
    float rstd = rsqrtf(var + 1e-5f);

    float4 gg = ((const float4*)(lng + (size_t)e * D_))[tid];
    float4 bb = ((const float4*)(lnb + (size_t)e * D_))[tid];
    __half2 h0 = __floats2half2_rn((v.x - mu) * rstd * gg.x + bb.x,
                                   (v.y - mu) * rstd * gg.y + bb.y);
    __half2 h1 = __floats2half2_rn((v.z - mu) * rstd * gg.z + bb.z,
                                   (v.w - mu) * rstd * gg.w + bb.w);
    __half2* dst = (__half2*)(g_hnh + (size_t)s * D_);
    dst[2 * tid]     = h0;
    dst[2 * tid + 1] = h1;
}

// ===================================================================
// Fused grouped GEMM pair, single launch (R9/R12 GEMM config).
// GEMM1 blocks: NO gating (w1 converted before launch via event).
// GEMM2 blocks: gate on g_w2cnt == NCHUNK (stealing w2 chunks from the
// ticket while waiting -> no dependence on worker co-scheduling), then
// the usual g_ready[ti] == 32 producer wait.
// CTA tile M=128 x N=128, K-stage 64, 3-stage cp.async, single barrier
// per stage, 96KB smem -> 2 CTAs/SM. 8 warps as 4(m) x 2(n), warp 32x64.
// ===================================================================

template<int KDIM>
__device__ __forceinline__ void issue_stage(const __half* __restrict__ Ag,
                                            const __half* __restrict__ Bg,
                                            int k0, int rendRel,
                                            uint32_t aBase, uint32_t bBase, int tid) {
#pragma unroll
    for (int i = 0; i < 4; i++) {           // A: 1024 cp16 (128 rows x 8 chunks)
        int idx = tid + i * 256;
        int row = idx >> 3, ch = idx & 7;
        uint32_t so = (uint32_t)row * 128 + (uint32_t)((ch ^ (row & 7)) << 4);
        cp16(aBase + so, Ag + (size_t)row * KDIM + k0 + ch * 8, row < rendRel);
    }
#pragma unroll
    for (int i = 0; i < 4; i++) {           // B: 1024 cp16
        int idx = tid + i * 256;
        int row = idx >> 3, ch = idx & 7;
        uint32_t so = (uint32_t)row * 128 + (uint32_t)((ch ^ (row & 7)) << 4);
        cp16(bBase + so, Bg + (size_t)row * KDIM + k0 + ch * 8, true);
    }
}

__device__ __forceinline__ void compute_stage64(uint32_t aB, uint32_t bB,
                                                float c[2][8][4],
                                                int wm, int wn) {
    int lane = threadIdx.x & 31;
    int lr = lane & 15;
    uint32_t khoff = (uint32_t)((lane >> 4) * 16);
#pragma unroll
    for (int kk = 0; kk < 4; kk++) {
        uint32_t low = khoff + (uint32_t)(kk * 32);
        uint32_t a0[4], a1[4];
        {
            int r = wm * 32 + lr;
            ldsm_x4(a0, aB + (uint32_t)r * 128 + (low ^ (uint32_t)((r & 7) << 4)));
        }
        {
            int r = wm * 32 + 16 + lr;
            ldsm_x4(a1, aB + (uint32_t)r * 128 + (low ^ (uint32_t)((r & 7) << 4)));
        }
#pragma unroll
        for (int ni2 = 0; ni2 < 4; ni2++) {
            uint32_t q[4];
            int r = wn * 64 + ni2 * 16 + lr;
            ldsm_x4(q, bB + (uint32_t)r * 128 + (low ^ (uint32_t)((r & 7) << 4)));
            uint32_t b0[2] = {q[0], q[2]};
            uint32_t b1[2] = {q[1], q[3]};
            mma_16x8x16(c[0][2 * ni2],     a0, b0);
            mma_16x8x16(c[1][2 * ni2],     a1, b0);
            mma_16x8x16(c[0][2 * ni2 + 1], a0, b1);
            mma_16x8x16(c[1][2 * ni2 + 1], a1, b1);
        }
    }
}

// GEMM2 gate: ensure w2 fully converted (stealing chunks while waiting)
__device__ __forceinline__ void gate_w2(int* shp, const float* __restrict__ w2src) {
    const float4* s4 = (const float4*)w2src;
    int tid = threadIdx.x;
    while (true) {
        if (tid == 0) {
            if (atomicAdd(&g_w2cnt, 0) >= NCHUNK) shp[0] = -1;
            else {
                int c = atomicAdd(&g_tick2, 1);
                shp[0] = (c < NCHUNK) ? c : -2;
            }
        }
        __syncthreads();
        int c = shp[0];
        __syncthreads();
        if (c == -1) break;
        if (c >= 0) {
            cvt_chunk_w2(s4, c, 256);
            __threadfence();
            __syncthreads();
            if (tid == 0) atomicAdd(&g_w2cnt, 1);
            __syncthreads();
        } else {
            __nanosleep(128);
        }
    }
}

template<int KDIM, bool SECOND>
__device__ __forceinline__ void gemm_body(int ti, int nblk, uint8_t* smem,
                                          const float* __restrict__ bias,
                                          const float* __restrict__ w2src,
                                          const float* __restrict__ x,
                                          float* __restrict__ out) {
    if (ti >= g_numTiles) return;
    int e = g_tileE[ti], row0 = g_tileRow[ti], rend = g_tileEnd[ti];
    int n0 = nblk * 128;
    int rendRel = rend - row0;
    constexpr int NOUT = SECOND ? D_ : F_;

    if (SECOND) {
        gate_w2((int*)smem, w2src);
        if (threadIdx.x == 0) {
            while (atomicAdd(&g_ready[ti], 0) < 32) __nanosleep(64);
        }
        __syncthreads();
    }

    const __half* Ag = (SECOND ? g_h1h : g_hnh) + (size_t)row0 * KDIM;
    const __half* Bg = (SECOND ? g_w2h : g_w1h) + (size_t)e * ((size_t)F_ * D_) + (size_t)n0 * KDIM;
    const float*  brow = bias + (size_t)e * NOUT + n0;

    uint32_t sb = smem_u32(smem);
    int tid = threadIdx.x, warp = tid >> 5, lane = tid & 31;
    int wm = warp >> 1, wn = warp & 1;
    int g = lane >> 2, tg = lane & 3;

    float c[2][8][4];
#pragma unroll
    for (int mi = 0; mi < 2; mi++)
#pragma unroll
        for (int ni = 0; ni < 8; ni++)
#pragma unroll
            for (int k = 0; k < 4; k++) c[mi][ni][k] = 0.f;

    constexpr int CH = KDIM / 64;

    // prologue: stages 0..1
#pragma unroll
    for (int s = 0; s < 2; s++) {
        issue_stage<KDIM>(Ag, Bg, s * 64, rendRel,
                          sb + s * STAGE_BYTES, sb + s * STAGE_BYTES + 16384, tid);
        cp_commit();
    }

    int s_c = 0, s_p = 2;
#pragma unroll 1
    for (int i = 0; i < CH; i++) {
        cp_wait<1>();
        __syncthreads();   // single barrier per stage
        if (i + 2 < CH) {
            issue_stage<KDIM>(Ag, Bg, (i + 2) * 64, rendRel,
                              sb + s_p * STAGE_BYTES, sb + s_p * STAGE_BYTES + 16384, tid);
        }
        cp_commit();   // uniform commit keeps wait<1> aligned near the tail
        compute_stage64(sb + s_c * STAGE_BYTES, sb + s_c * STAGE_BYTES + 16384, c, wm, wn);
        s_c = (s_c == 2) ? 0 : s_c + 1;
        s_p = (s_p == 2) ? 0 : s_p + 1;
    }

    // ---------------- epilogue ----------------
    if (!SECOND) {
#pragma unroll
        for (int ni = 0; ni < 8; ni++) {
            int col = n0 + wn * 64 + ni * 8 + 2 * tg;
            float bi0 = __ldg(&brow[wn * 64 + ni * 8 + 2 * tg]);
            float bi1 = __ldg(&brow[wn * 64 + ni * 8 + 2 * tg + 1]);
#pragma unroll
            for (int mi = 0; mi < 2; mi++) {
                int r = row0 + wm * 32 + mi * 16 + g;
                *(__half2*)(g_h1h + (size_t)r * F_ + col) =
                    __floats2half2_rn(fmaxf(c[mi][ni][0] + bi0, 0.f),
                                      fmaxf(c[mi][ni][1] + bi1, 0.f));
                *(__half2*)(g_h1h + (size_t)(r + 8) * F_ + col) =
                    __floats2half2_rn(fmaxf(c[mi][ni][2] + bi0, 0.f),
                                      fmaxf(c[mi][ni][3] + bi1, 0.f));
            }
        }
        __threadfence();
        __syncthreads();
        if (tid == 0) atomicAdd(&g_ready[ti], 1);
    } else {
#pragma unroll
        for (int ni = 0; ni < 8; ni++) {
            int col = n0 + wn * 64 + ni * 8 + 2 * tg;
            float bi0 = __ldg(&brow[wn * 64 + ni * 8 + 2 * tg]);
            float bi1 = __ldg(&brow[wn * 64 + ni * 8 + 2 * tg + 1]);
#pragma unroll
            for (int mi = 0; mi < 2; mi++) {
                int r = row0 + wm * 32 + mi * 16 + g;
                if (r < rend) {
                    int t = g_srt[r];
                    float al = g_alpha[t];
                    float2 xv = *(const float2*)(x + (size_t)t * D_ + col);
                    float2 o;
                    o.x = xv.x + al * (c[mi][ni][0] + bi0);
                    o.y = xv.y + al * (c[mi][ni][1] + bi1);
                    *(float2*)(out + (size_t)t * D_ + col) = o;
                }
                if (r + 8 < rend) {
                    int t = g_srt[r + 8];
                    float al = g_alpha[t];
                    float2 xv = *(const float2*)(x + (size_t)t * D_ + col);
                    float2 o;
                    o.x = xv.x + al * (c[mi][ni][2] + bi0);
                    o.y = xv.y + al * (c[mi][ni][3] + bi1);
                    *(float2*)(out + (size_t)t * D_ + col) = o;
                }
            }
        }
    }
}

__global__ __launch_bounds__(256, 2) void fused_gemm(const float* __restrict__ b1,
                                                     const float* __restrict__ b2,
                                                     const float* __restrict__ w2src,
                                                     const float* __restrict__ x,
                                                     float* __restrict__ out) {
    extern __shared__ __align__(1024) uint8_t smem[];
    int bid = blockIdx.x;
    if (bid < G1BLKS) {
        gemm_body<D_, false>(bid >> 5, bid & 31, smem, b1, w2src, x, out);
    } else {
        int r = bid - G1BLKS;
        gemm_body<F_, true>(r >> 3, r & 7, smem, b2, w2src, x, out);
    }
}

// ------------------- launch -------------------
extern "C" void kernel_launch(void* const* d_in, const int* in_sizes, int n_in,
                              void* d_out, int out_size) {
    const float* x    = (const float*)d_in[0];
    const float* cent = (const float*)d_in[1];
    const float* lng  = (const float*)d_in[2];
    const float* lnb  = (const float*)d_in[3];
    const float* w1   = (const float*)d_in[4];
    const float* b1   = (const float*)d_in[5];
    const float* w2   = (const float*)d_in[6];
    const float* b2   = (const float*)d_in[7];
    float* out = (float*)d_out;

    static cudaStream_t sA = nullptr;
    static cudaEvent_t eFork = nullptr, eW1 = nullptr, eC2 = nullptr;
    if (!sA) {
        cudaStreamCreateWithFlags(&sA, cudaStreamNonBlocking);
        cudaEventCreateWithFlags(&eFork, cudaEventDisableTiming);
        cudaEventCreateWithFlags(&eW1, cudaEventDisableTiming);
        cudaEventCreateWithFlags(&eC2, cudaEventDisableTiming);
        cudaFuncSetAttribute(fused_gemm, cudaFuncAttributeMaxDynamicSharedMemorySize, SMEM_TOTAL);
    }

    // init first (ticket/counters), then fork the weight pipeline onto sA:
    // w1 converts ALONE at full HBM bandwidth; then ONE trickle worker block
    // per SM converts w2 co-resident with the fused GEMM (zero smem, 8 warps).
    init_kernel<<<1, 128>>>();
    cudaEventRecord(eFork, 0);
    cudaStreamWaitEvent(sA, eFork, 0);
    convert_w1<<<4096, 256, 0, sA>>>(w1);
    cudaEventRecord(eW1, sA);
    cvt_worker_w2<<<148, 256, 0, sA>>>(w2);
    cudaEventRecord(eC2, sA);

    // routing chain on main stream (overlaps w1 convert)
    routing_kernel<<<T_ / 16, 256>>>(x, cent);
    scan_kernel<<<1, 1>>>();
    ln_kernel<<<T_, 256>>>(x, lng, lnb);

    // fused GEMMs: gate only on w1 (event); w2 is gated in-kernel by GEMM2
    cudaStreamWaitEvent(0, eW1, 0);
    fused_gemm<<<G1BLKS + 8 * MAX_TILES, 256, SMEM_TOTAL>>>(b1, b2, w2, x, out);

    // join the worker stream (after the fused launch; non-serializing)
    cudaStreamWaitEvent(0, eC2, 0);
}